// round 3
// baseline (speedup 1.0000x reference)
#include <cuda_runtime.h>
#include <math.h>

#define S 8192
#define DM 768
#define DR 1024
#define MI 3072

// ------------------- scratch (device globals; no allocs allowed) -------------------
__device__ float g_h[S * DM];            // rmsnorm output (reused for h2)
__device__ float g_ab[S * 2 * DR];       // lin1 output
__device__ float g_abr[S * DR];          // gelu(a branch)
__device__ float g_conv[S * DR];         // conv output
__device__ float g_gates[S * 2 * DR];    // sigmoid gates
__device__ float g_a[S * DR];            // recurrence decay a_t
__device__ float g_gx[S * DR];           // gated_x  (later reused for a_branch*y)
__device__ float g_y[S * DR];            // scan output
__device__ float g_x2[S * DM];           // x + tempmix
__device__ float g_m[S * 2 * MI];        // mlp lin1 output
__device__ float g_mi[S * MI];           // glu output
__device__ float g_wk[4 * DR * DR];      // repacked conv weights [seg][o][i]
#define NCHUNK 64
#define SCHUNK 128
__device__ float g_Ag[NCHUNK * DR];
__device__ float g_Bg[NCHUNK * DR];
__device__ float g_carry[NCHUNK * DR];

// ------------------- math helpers -------------------
__device__ __forceinline__ float gelu_f(float x) {
    // jax.nn.gelu default (approximate=True, tanh form)
    float x3 = x * x * x;
    return 0.5f * x * (1.0f + tanhf(0.7978845608028654f * (x + 0.044715f * x3)));
}
__device__ __forceinline__ float sigmoid_f(float x) {
    return 1.0f / (1.0f + expf(-x));
}

// ------------------- RMSNorm -------------------
__global__ __launch_bounds__(256) void rmsnorm_k(const float* __restrict__ x,
                                                 const float* __restrict__ w,
                                                 float* __restrict__ o, int D) {
    int row = blockIdx.x;
    const float* xr = x + (size_t)row * D;
    float s = 0.f;
    for (int i = threadIdx.x; i < D; i += 256) {
        float v = xr[i];
        s += v * v;
    }
    __shared__ float sm[8];
    __shared__ float s_inv;
    for (int off = 16; off; off >>= 1) s += __shfl_down_sync(0xffffffffu, s, off);
    if ((threadIdx.x & 31) == 0) sm[threadIdx.x >> 5] = s;
    __syncthreads();
    if (threadIdx.x == 0) {
        float t = 0.f;
#pragma unroll
        for (int i = 0; i < 8; i++) t += sm[i];
        s_inv = rsqrtf(t / (float)D + 1e-5f);
    }
    __syncthreads();
    float inv = s_inv;
    float* orow = o + (size_t)row * D;
    for (int i = threadIdx.x; i < D; i += 256) orow[i] = xr[i] * inv * w[i];
}

// ------------------- generic SGEMM: C[M,N] = A[M,K] @ W[N,K]^T (+epilogue) ---------
// EPI: 0 = +bias ; 1 = sigmoid(+bias) ; 2 = +bias + residual
template <int EPI>
__global__ __launch_bounds__(256) void sgemm_nt(const float* __restrict__ A, int lda,
                                                const float* __restrict__ W,
                                                const float* __restrict__ bias,
                                                const float* __restrict__ res,
                                                float* __restrict__ C, int ldc,
                                                int M, int N, int K) {
    __shared__ __align__(16) float As[8][128];
    __shared__ __align__(16) float Ws[8][128];
    int tid = threadIdx.x;
    int bm = blockIdx.y * 128;
    int bn = blockIdx.x * 128;
    int lr = tid >> 1;
    int lk = (tid & 1) * 4;
    int tm = (tid >> 4) << 3;
    int tn = (tid & 15) << 3;
    const float* Aload = A + (size_t)(bm + lr) * lda + lk;
    const float* Wload = W + (size_t)(bn + lr) * K + lk;
    float acc[8][8];
#pragma unroll
    for (int i = 0; i < 8; i++)
#pragma unroll
        for (int j = 0; j < 8; j++) acc[i][j] = 0.f;

    for (int k0 = 0; k0 < K; k0 += 8) {
        float4 av = *(const float4*)(Aload + k0);
        float4 wv = *(const float4*)(Wload + k0);
        __syncthreads();
        As[lk + 0][lr] = av.x; As[lk + 1][lr] = av.y;
        As[lk + 2][lr] = av.z; As[lk + 3][lr] = av.w;
        Ws[lk + 0][lr] = wv.x; Ws[lk + 1][lr] = wv.y;
        Ws[lk + 2][lr] = wv.z; Ws[lk + 3][lr] = wv.w;
        __syncthreads();
#pragma unroll
        for (int kk = 0; kk < 8; kk++) {
            float4 a0 = *(const float4*)&As[kk][tm];
            float4 a1 = *(const float4*)&As[kk][tm + 4];
            float4 b0 = *(const float4*)&Ws[kk][tn];
            float4 b1 = *(const float4*)&Ws[kk][tn + 4];
            float ar[8] = {a0.x, a0.y, a0.z, a0.w, a1.x, a1.y, a1.z, a1.w};
            float br[8] = {b0.x, b0.y, b0.z, b0.w, b1.x, b1.y, b1.z, b1.w};
#pragma unroll
            for (int i = 0; i < 8; i++)
#pragma unroll
                for (int j = 0; j < 8; j++) acc[i][j] = fmaf(ar[i], br[j], acc[i][j]);
        }
    }
#pragma unroll
    for (int i = 0; i < 8; i++) {
        int row = bm + tm + i;
        float* crow = C + (size_t)row * ldc + bn + tn;
        const float* rrow = res ? (res + (size_t)row * ldc + bn + tn) : nullptr;
#pragma unroll
        for (int j = 0; j < 8; j++) {
            int col = bn + tn + j;
            float v = acc[i][j] + bias[col];
            if (EPI == 1) v = sigmoid_f(v);
            if (EPI == 2) v += rrow[j];
            crow[j] = v;
        }
    }
}

// ------------------- conv-as-GEMM: g_conv = sum_k shift(b_branch,3-k) @ Wk^T -------
__global__ __launch_bounds__(256) void conv_gemm_k() {
    __shared__ __align__(16) float As[8][128];
    __shared__ __align__(16) float Ws[8][128];
    int tid = threadIdx.x;
    int bm = blockIdx.y * 128;
    int bn = blockIdx.x * 128;
    int lr = tid >> 1;
    int lk = (tid & 1) * 4;
    int tm = (tid >> 4) << 3;
    int tn = (tid & 15) << 3;
    float acc[8][8];
#pragma unroll
    for (int i = 0; i < 8; i++)
#pragma unroll
        for (int j = 0; j < 8; j++) acc[i][j] = 0.f;

    for (int k0 = 0; k0 < 4 * DR; k0 += 8) {
        int seg = k0 >> 10;
        int kin = k0 & (DR - 1);
        int shift = 3 - seg;
        int rA = bm + lr - shift;
        float4 av;
        if (rA >= 0)
            av = *(const float4*)&g_ab[(size_t)rA * (2 * DR) + DR + kin + lk];
        else
            av = make_float4(0.f, 0.f, 0.f, 0.f);
        float4 wv = *(const float4*)&g_wk[(size_t)seg * DR * DR + (size_t)(bn + lr) * DR + kin + lk];
        __syncthreads();
        As[lk + 0][lr] = av.x; As[lk + 1][lr] = av.y;
        As[lk + 2][lr] = av.z; As[lk + 3][lr] = av.w;
        Ws[lk + 0][lr] = wv.x; Ws[lk + 1][lr] = wv.y;
        Ws[lk + 2][lr] = wv.z; Ws[lk + 3][lr] = wv.w;
        __syncthreads();
#pragma unroll
        for (int kk = 0; kk < 8; kk++) {
            float4 a0 = *(const float4*)&As[kk][tm];
            float4 a1 = *(const float4*)&As[kk][tm + 4];
            float4 b0 = *(const float4*)&Ws[kk][tn];
            float4 b1 = *(const float4*)&Ws[kk][tn + 4];
            float ar[8] = {a0.x, a0.y, a0.z, a0.w, a1.x, a1.y, a1.z, a1.w};
            float br[8] = {b0.x, b0.y, b0.z, b0.w, b1.x, b1.y, b1.z, b1.w};
#pragma unroll
            for (int i = 0; i < 8; i++)
#pragma unroll
                for (int j = 0; j < 8; j++) acc[i][j] = fmaf(ar[i], br[j], acc[i][j]);
        }
    }
#pragma unroll
    for (int i = 0; i < 8; i++) {
        int row = bm + tm + i;
#pragma unroll
        for (int j = 0; j < 8; j++) g_conv[(size_t)row * DR + bn + tn + j] = acc[i][j];
    }
}

// ------------------- small elementwise kernels -------------------
__global__ __launch_bounds__(256) void repack_wconv_k(const float* __restrict__ w_conv) {
    int i = blockIdx.x * 256 + threadIdx.x;
    if (i >= 4 * DR * DR) return;
    int seg = i >> 20;
    int rem = i & ((1 << 20) - 1);
    int n = rem >> 10;
    int kin = rem & 1023;
    g_wk[i] = w_conv[(size_t)n * (DR * 4) + kin * 4 + seg];
}

__global__ __launch_bounds__(256) void gelu_abranch_k() {
    int i = blockIdx.x * 256 + threadIdx.x;
    if (i >= S * DR) return;
    int t = i >> 10;
    int c = i & (DR - 1);
    g_abr[i] = gelu_f(g_ab[(size_t)t * (2 * DR) + c]);
}

__global__ __launch_bounds__(256) void gates_proc_k(const float* __restrict__ Lambda) {
    int i = blockIdx.x * 256 + threadIdx.x;
    if (i >= S * DR) return;
    int t = i >> 10;
    int c = i & (DR - 1);
    float ig = g_gates[(size_t)t * (2 * DR) + c];
    float rg = g_gates[(size_t)t * (2 * DR) + DR + c];
    float L = Lambda[c];
    float sp = log1pf(expf(L));
    float a = expf(-8.0f * sp * rg);
    float gx = sqrtf(fmaxf(1.0f - a * a, 0.0f)) * ig * g_conv[i];
    g_a[i] = a;
    g_gx[i] = gx;
}

__global__ __launch_bounds__(256) void ya_k() {
    int i = blockIdx.x * 256 + threadIdx.x;
    if (i >= S * DR) return;
    g_gx[i] = g_abr[i] * g_y[i];   // reuse g_gx as (a_branch * y)
}

__global__ __launch_bounds__(256) void glu_k() {
    int i = blockIdx.x * 256 + threadIdx.x;
    if (i >= S * MI) return;
    int t = i / MI;
    int c = i - t * MI;
    float u = g_m[(size_t)t * (2 * MI) + c];
    float v = g_m[(size_t)t * (2 * MI) + MI + c];
    g_mi[i] = gelu_f(u) * v;
}

// ------------------- chunked linear-recurrence scan -------------------
__global__ __launch_bounds__(256) void scan_pass1_k() {
    int c = blockIdx.y * 256 + threadIdx.x;
    int j = blockIdx.x;
    size_t base = (size_t)j * SCHUNK * DR + c;
    float A = 1.f, B = 0.f;
#pragma unroll 4
    for (int t = 0; t < SCHUNK; t++) {
        float at = g_a[base + (size_t)t * DR];
        float gx = g_gx[base + (size_t)t * DR];
        B = fmaf(at, B, gx);
        A *= at;
    }
    g_Ag[j * DR + c] = A;
    g_Bg[j * DR + c] = B;
}
__global__ __launch_bounds__(256) void scan_pass2_k() {
    int c = blockIdx.x * 256 + threadIdx.x;
    float h = 0.f;
    for (int j = 0; j < NCHUNK; j++) {
        g_carry[j * DR + c] = h;
        h = fmaf(g_Ag[j * DR + c], h, g_Bg[j * DR + c]);
    }
}
__global__ __launch_bounds__(256) void scan_pass3_k() {
    int c = blockIdx.y * 256 + threadIdx.x;
    int j = blockIdx.x;
    size_t base = (size_t)j * SCHUNK * DR + c;
    float h = g_carry[j * DR + c];
#pragma unroll 4
    for (int t = 0; t < SCHUNK; t++) {
        float at = g_a[base + (size_t)t * DR];
        float gx = g_gx[base + (size_t)t * DR];
        h = fmaf(at, h, gx);
        g_y[base + (size_t)t * DR] = h;
    }
}

// ------------------- launch -------------------
extern "C" void kernel_launch(void* const* d_in, const int* in_sizes, int n_in,
                              void* d_out, int out_size) {
    const float* x      = (const float*)d_in[0];
    const float* w_n1   = (const float*)d_in[1];
    const float* w_n2   = (const float*)d_in[2];
    const float* w_lin1 = (const float*)d_in[3];
    const float* b_lin1 = (const float*)d_in[4];
    const float* w_conv = (const float*)d_in[5];
    const float* w_rg   = (const float*)d_in[6];
    const float* b_rg   = (const float*)d_in[7];
    const float* Lambda = (const float*)d_in[8];
    const float* w_out  = (const float*)d_in[9];
    const float* b_out  = (const float*)d_in[10];
    const float* w_m1   = (const float*)d_in[11];
    const float* b_m1   = (const float*)d_in[12];
    const float* w_m2   = (const float*)d_in[13];
    const float* b_m2   = (const float*)d_in[14];
    float* out = (float*)d_out;

    float *p_h, *p_ab, *p_gx, *p_gates, *p_conv, *p_x2, *p_m, *p_mi;
    cudaGetSymbolAddress((void**)&p_h, g_h);
    cudaGetSymbolAddress((void**)&p_ab, g_ab);
    cudaGetSymbolAddress((void**)&p_gx, g_gx);
    cudaGetSymbolAddress((void**)&p_gates, g_gates);
    cudaGetSymbolAddress((void**)&p_conv, g_conv);
    cudaGetSymbolAddress((void**)&p_x2, g_x2);
    cudaGetSymbolAddress((void**)&p_m, g_m);
    cudaGetSymbolAddress((void**)&p_mi, g_mi);

    // 1) h = rmsnorm(x, w_n1)
    rmsnorm_k<<<S, 256>>>(x, w_n1, p_h, DM);
    // 2) ab = h @ w_lin1^T + b_lin1
    sgemm_nt<0><<<dim3(2 * DR / 128, S / 128), 256>>>(p_h, DM, w_lin1, b_lin1, nullptr,
                                                      p_ab, 2 * DR, S, 2 * DR, DM);
    // 3) a_branch = gelu(ab[:, :DR])
    gelu_abranch_k<<<(S * DR + 255) / 256, 256>>>();
    // 4) repack conv weights
    repack_wconv_k<<<(4 * DR * DR + 255) / 256, 256>>>(w_conv);
    // 5) conv = causal conv over b_branch (fused 4-tap GEMM, K=4096)
    conv_gemm_k<<<dim3(DR / 128, S / 128), 256>>>();
    // 6) gates = sigmoid(conv @ w_rg^T + b_rg)
    sgemm_nt<1><<<dim3(2 * DR / 128, S / 128), 256>>>(p_conv, DR, w_rg, b_rg, nullptr,
                                                      p_gates, 2 * DR, S, 2 * DR, DR);
    // 7) a, gated_x
    gates_proc_k<<<(S * DR + 255) / 256, 256>>>(Lambda);
    // 8) linear recurrence scan
    scan_pass1_k<<<dim3(NCHUNK, DR / 256), 256>>>();
    scan_pass2_k<<<DR / 256, 256>>>();
    scan_pass3_k<<<dim3(NCHUNK, DR / 256), 256>>>();
    // 9) ya = a_branch * y  (into g_gx)
    ya_k<<<(S * DR + 255) / 256, 256>>>();
    // 10) x2 = x + ya @ w_out^T + b_out
    sgemm_nt<2><<<dim3(DM / 128, S / 128), 256>>>(p_gx, DR, w_out, b_out, x,
                                                  p_x2, DM, S, DM, DR);
    // 11) h2 = rmsnorm(x2, w_n2)  (reuse g_h)
    rmsnorm_k<<<S, 256>>>(p_x2, w_n2, p_h, DM);
    // 12) m = h2 @ w_m1^T + b_m1
    sgemm_nt<0><<<dim3(2 * MI / 128, S / 128), 256>>>(p_h, DM, w_m1, b_m1, nullptr,
                                                      p_m, 2 * MI, S, 2 * MI, DM);
    // 13) mi = gelu(m[:, :MI]) * m[:, MI:]
    glu_k<<<(S * MI + 255) / 256, 256>>>();
    // 14) out = x2 + mi @ w_m2^T + b_m2
    sgemm_nt<2><<<dim3(DM / 128, S / 128), 256>>>(p_mi, MI, w_m2, b_m2, p_x2,
                                                  out, DM, S, DM, MI);
}

// round 8
// speedup vs baseline: 3.4555x; 3.4555x over previous
#include <cuda_runtime.h>
#include <math.h>
#include <stdint.h>

#define S 8192
#define DM 768
#define DR 1024
#define MI 3072

// ------------------- scratch (device globals; no allocs allowed) -------------------
__device__ float g_h[S * DM];
__device__ float g_ab[S * 2 * DR];
__device__ float g_abr[S * DR];
__device__ float g_conv[S * DR];
__device__ float g_gates[S * 2 * DR];
__device__ float g_a[S * DR];
__device__ float g_gx[S * DR];
__device__ float g_y[S * DR];
__device__ float g_x2[S * DM];
__device__ float g_m[S * 2 * MI];
__device__ float g_mi[S * MI];
__device__ float g_wk[DR * 4 * DR];       // conv weights repacked [N=1024][K=4096], tf32-rounded
__device__ float g_wlin1[2 * DR * DM];    // tf32-rounded weight copies
__device__ float g_wrg[2 * DR * DR];
__device__ float g_wout[DM * DR];
__device__ float g_wm1[2 * MI * DM];
__device__ float g_wm2[DM * MI];
#define NCHUNK 64
#define SCHUNK 128
__device__ float g_Ag[NCHUNK * DR];
__device__ float g_Bg[NCHUNK * DR];
__device__ float g_carry[NCHUNK * DR];

// ------------------- math helpers -------------------
__device__ __forceinline__ float gelu_f(float x) {
    float x3 = x * x * x;
    return 0.5f * x * (1.0f + tanhf(0.7978845608028654f * (x + 0.044715f * x3)));
}
__device__ __forceinline__ float sigmoid_f(float x) { return 1.0f / (1.0f + expf(-x)); }
__device__ __forceinline__ float tf32r(float x) {
    uint32_t u;
    asm("cvt.rna.tf32.f32 %0, %1;" : "=r"(u) : "f"(x));
    return __uint_as_float(u);
}

// ------------------- cp.async helpers -------------------
__device__ __forceinline__ uint32_t smem_u32(const void* p) {
    uint32_t a;
    asm("{ .reg .u64 t; cvta.to.shared.u64 t, %1; cvt.u32.u64 %0, t; }" : "=r"(a) : "l"(p));
    return a;
}
#define CP16(dst, src) \
    asm volatile("cp.async.cg.shared.global [%0], [%1], 16;" :: "r"(dst), "l"(src))
#define CP16_ZFILL(dst, src) \
    asm volatile("cp.async.cg.shared.global [%0], [%1], 16, 0;" :: "r"(dst), "l"(src))
#define CP_COMMIT() asm volatile("cp.async.commit_group;" ::: "memory")
#define CP_WAIT(n) asm volatile("cp.async.wait_group %0;" :: "n"(n) : "memory")

// ------------------- tf32 mma.sync -------------------
__device__ __forceinline__ void mma_tf32(float* c, const uint32_t* a, const uint32_t* b) {
    asm volatile(
        "mma.sync.aligned.m16n8k8.row.col.f32.tf32.tf32.f32 "
        "{%0,%1,%2,%3}, {%4,%5,%6,%7}, {%8,%9}, {%0,%1,%2,%3};"
        : "+f"(c[0]), "+f"(c[1]), "+f"(c[2]), "+f"(c[3])
        : "r"(a[0]), "r"(a[1]), "r"(a[2]), "r"(a[3]), "r"(b[0]), "r"(b[1]));
}

// ------------------- tf32 GEMM: C[M,N] = A[M,K] @ W[N,K]^T (+epilogue) -------------------
// Tile 128x128x32, 3-stage cp.async pipeline, 256 threads = 2x4 warps, warp tile 64x32.
// EPI: 0 = plain store rounded to tf32 (conv)
//      1 = +bias (m1)
//      2 = sigmoid(+bias) (rg)
//      3 = +bias + residual (out, m2)
//      4 = +bias, store rounded to tf32, gelu side-store for cols<DR (lin1)
#define STAGES 3
#define SK 36                      // padded K stride in floats (32 + 4)
#define ASTG (128 * SK)            // floats per stage (A or B)

template <int EPI>
__global__ void __launch_bounds__(256, 2)
tc_gemm(const float* __restrict__ A, int lda,
        const float* __restrict__ W,
        const float* __restrict__ bias, const float* __restrict__ res,
        float* __restrict__ C, int ldc, float* __restrict__ gelu_out,
        int K, int shifted) {
    extern __shared__ float sm[];
    float* sA = sm;
    float* sB = sm + STAGES * ASTG;
    const int tid = threadIdx.x, lane = tid & 31, wid = tid >> 5;
    const int wm = wid & 1, wn = wid >> 1, laneg = lane >> 2, lanet = lane & 3;
    const int bm = blockIdx.y * 128, bn = blockIdx.x * 128;
    const int ktiles = K >> 5;
    const uint32_t sAaddr = smem_u32(sA), sBaddr = smem_u32(sB);

    float acc[4][4][4];
#pragma unroll
    for (int i = 0; i < 4; i++)
#pragma unroll
        for (int j = 0; j < 4; j++)
#pragma unroll
            for (int t = 0; t < 4; t++) acc[i][j][t] = 0.f;

    auto load_stage = [&](int kt, int st) {
#pragma unroll
        for (int i = 0; i < 4; i++) {                 // A: 1024 16B chunks
            int c = tid + 256 * i;
            int row = c >> 3, kc = c & 7;
            int grow, gcol;
            if (shifted) { int seg = kt >> 5; grow = bm + row + seg - 3; gcol = ((kt & 31) << 5) + (kc << 2); }
            else { grow = bm + row; gcol = (kt << 5) + (kc << 2); }
            uint32_t dst = sAaddr + (uint32_t)(st * ASTG + row * SK + (kc << 2)) * 4u;
            const float* src = A + (size_t)grow * lda + gcol;
            if (shifted && grow < 0) CP16_ZFILL(dst, A);
            else CP16(dst, src);
        }
#pragma unroll
        for (int i = 0; i < 4; i++) {                 // B: 1024 16B chunks
            int c = tid + 256 * i;
            int row = c >> 3, kc = c & 7;
            uint32_t dst = sBaddr + (uint32_t)(st * ASTG + row * SK + (kc << 2)) * 4u;
            const float* src = W + (size_t)(bn + row) * K + (kt << 5) + (kc << 2);
            CP16(dst, src);
        }
    };

    auto compute_stage = [&](int st) {
        const float* a_ = sA + st * ASTG;
        const float* b_ = sB + st * ASTG;
#pragma unroll
        for (int k8 = 0; k8 < 4; k8++) {
            int k0 = k8 * 8;
            uint32_t af[4][4], bf[4][2];
#pragma unroll
            for (int mf = 0; mf < 4; mf++) {
                int r = (wm * 64 + mf * 16 + laneg) * SK + lanet + k0;
                af[mf][0] = __float_as_uint(a_[r]);
                af[mf][1] = __float_as_uint(a_[r + 8 * SK]);
                af[mf][2] = __float_as_uint(a_[r + 4]);
                af[mf][3] = __float_as_uint(a_[r + 8 * SK + 4]);
            }
#pragma unroll
            for (int nf = 0; nf < 4; nf++) {
                int r = (wn * 32 + nf * 8 + laneg) * SK + lanet + k0;
                bf[nf][0] = __float_as_uint(b_[r]);
                bf[nf][1] = __float_as_uint(b_[r + 4]);
            }
#pragma unroll
            for (int mf = 0; mf < 4; mf++)
#pragma unroll
                for (int nf = 0; nf < 4; nf++) mma_tf32(acc[mf][nf], af[mf], bf[nf]);
        }
    };

    // prologue
#pragma unroll
    for (int s = 0; s < STAGES - 1; s++) {
        load_stage(s, s);
        CP_COMMIT();
    }
    // mainloop
    for (int kt = 0; kt < ktiles; kt++) {
        CP_WAIT(1);
        __syncthreads();
        int nk = kt + STAGES - 1;
        if (nk < ktiles) load_stage(nk, nk % STAGES);
        CP_COMMIT();
        compute_stage(kt % STAGES);
    }
    CP_WAIT(0);

    // epilogue
#pragma unroll
    for (int mf = 0; mf < 4; mf++) {
#pragma unroll
        for (int half = 0; half < 2; half++) {
            int row = bm + wm * 64 + mf * 16 + laneg + half * 8;
            size_t crow = (size_t)row * ldc;
#pragma unroll
            for (int nf = 0; nf < 4; nf++) {
                int col = bn + wn * 32 + nf * 8 + lanet * 2;
                float v0 = acc[mf][nf][half * 2];
                float v1 = acc[mf][nf][half * 2 + 1];
                if (EPI != 0) { v0 += bias[col]; v1 += bias[col + 1]; }
                if (EPI == 2) { v0 = sigmoid_f(v0); v1 = sigmoid_f(v1); }
                if (EPI == 3) { v0 += res[crow + col]; v1 += res[crow + col + 1]; }
                if (EPI == 4 && col < DR) {
                    float2 g = make_float2(gelu_f(v0), gelu_f(v1));
                    *(float2*)&gelu_out[(size_t)row * DR + col] = g;
                }
                if (EPI == 0 || EPI == 4) { v0 = tf32r(v0); v1 = tf32r(v1); }
                *(float2*)&C[crow + col] = make_float2(v0, v1);
            }
        }
    }
}

// ------------------- RMSNorm (output rounded to tf32: feeds GEMMs) -------------------
__global__ __launch_bounds__(256) void rmsnorm_k(const float* __restrict__ x,
                                                 const float* __restrict__ w,
                                                 float* __restrict__ o, int D) {
    int row = blockIdx.x;
    const float* xr = x + (size_t)row * D;
    float s = 0.f;
    for (int i = threadIdx.x; i < D; i += 256) { float v = xr[i]; s += v * v; }
    __shared__ float sm[8];
    __shared__ float s_inv;
    for (int off = 16; off; off >>= 1) s += __shfl_down_sync(0xffffffffu, s, off);
    if ((threadIdx.x & 31) == 0) sm[threadIdx.x >> 5] = s;
    __syncthreads();
    if (threadIdx.x == 0) {
        float t = 0.f;
#pragma unroll
        for (int i = 0; i < 8; i++) t += sm[i];
        s_inv = rsqrtf(t / (float)D + 1e-5f);
    }
    __syncthreads();
    float inv = s_inv;
    float* orow = o + (size_t)row * D;
    for (int i = threadIdx.x; i < D; i += 256) orow[i] = tf32r(xr[i] * inv * w[i]);
}

// ------------------- elementwise kernels -------------------
__global__ __launch_bounds__(256) void cvt_copy_k(const float* __restrict__ src,
                                                  float* __restrict__ dst, int n) {
    int i = (blockIdx.x * 256 + threadIdx.x) * 4;
    if (i >= n) return;
    float4 v = *(const float4*)(src + i);
    v.x = tf32r(v.x); v.y = tf32r(v.y); v.z = tf32r(v.z); v.w = tf32r(v.w);
    *(float4*)(dst + i) = v;
}

__global__ __launch_bounds__(256) void repack_wconv_k(const float* __restrict__ w_conv) {
    int i = blockIdx.x * 256 + threadIdx.x;
    if (i >= DR * 4 * DR) return;
    int n = i >> 12;
    int rem = i & 4095;
    int t = rem >> 10;
    int kin = rem & 1023;
    g_wk[i] = tf32r(w_conv[((size_t)n << 12) + (kin << 2) + t]);
}

__global__ __launch_bounds__(256) void gates_proc_k(const float* __restrict__ Lambda) {
    int i = blockIdx.x * 256 + threadIdx.x;
    if (i >= S * DR) return;
    int t = i >> 10;
    int c = i & (DR - 1);
    float ig = g_gates[(size_t)t * (2 * DR) + c];
    float rg = g_gates[(size_t)t * (2 * DR) + DR + c];
    float L = Lambda[c];
    float sp = log1pf(expf(L));
    float a = expf(-8.0f * sp * rg);
    float gx = sqrtf(fmaxf(1.0f - a * a, 0.0f)) * ig * g_conv[i];
    g_a[i] = a;
    g_gx[i] = gx;
}

__global__ __launch_bounds__(256) void ya_k() {
    int i = blockIdx.x * 256 + threadIdx.x;
    if (i >= S * DR) return;
    g_gx[i] = tf32r(g_abr[i] * g_y[i]);   // feeds out-GEMM as A operand
}

__global__ __launch_bounds__(256) void glu_k() {
    int i = blockIdx.x * 256 + threadIdx.x;
    if (i >= S * MI) return;
    int t = i / MI;
    int c = i - t * MI;
    float u = g_m[(size_t)t * (2 * MI) + c];
    float v = g_m[(size_t)t * (2 * MI) + MI + c];
    g_mi[i] = tf32r(gelu_f(u) * v);       // feeds m2-GEMM as A operand
}

// ------------------- chunked linear-recurrence scan -------------------
__global__ __launch_bounds__(256) void scan_pass1_k() {
    int c = blockIdx.y * 256 + threadIdx.x;
    int j = blockIdx.x;
    size_t base = (size_t)j * SCHUNK * DR + c;
    float A = 1.f, B = 0.f;
#pragma unroll 4
    for (int t = 0; t < SCHUNK; t++) {
        float at = g_a[base + (size_t)t * DR];
        float gx = g_gx[base + (size_t)t * DR];
        B = fmaf(at, B, gx);
        A *= at;
    }
    g_Ag[j * DR + c] = A;
    g_Bg[j * DR + c] = B;
}
__global__ __launch_bounds__(256) void scan_pass2_k() {
    int c = blockIdx.x * 256 + threadIdx.x;
    float h = 0.f;
    for (int j = 0; j < NCHUNK; j++) {
        g_carry[j * DR + c] = h;
        h = fmaf(g_Ag[j * DR + c], h, g_Bg[j * DR + c]);
    }
}
__global__ __launch_bounds__(256) void scan_pass3_k() {
    int c = blockIdx.y * 256 + threadIdx.x;
    int j = blockIdx.x;
    size_t base = (size_t)j * SCHUNK * DR + c;
    float h = g_carry[j * DR + c];
#pragma unroll 4
    for (int t = 0; t < SCHUNK; t++) {
        float at = g_a[base + (size_t)t * DR];
        float gx = g_gx[base + (size_t)t * DR];
        h = fmaf(at, h, gx);
        g_y[base + (size_t)t * DR] = h;
    }
}

// ------------------- launch -------------------
#define SMEM_BYTES (STAGES * ASTG * 2 * 4)

extern "C" void kernel_launch(void* const* d_in, const int* in_sizes, int n_in,
                              void* d_out, int out_size) {
    const float* x      = (const float*)d_in[0];
    const float* w_n1   = (const float*)d_in[1];
    const float* w_n2   = (const float*)d_in[2];
    const float* w_lin1 = (const float*)d_in[3];
    const float* b_lin1 = (const float*)d_in[4];
    const float* w_conv = (const float*)d_in[5];
    const float* w_rg   = (const float*)d_in[6];
    const float* b_rg   = (const float*)d_in[7];
    const float* Lambda = (const float*)d_in[8];
    const float* w_out  = (const float*)d_in[9];
    const float* b_out  = (const float*)d_in[10];
    const float* w_m1   = (const float*)d_in[11];
    const float* b_m1   = (const float*)d_in[12];
    const float* w_m2   = (const float*)d_in[13];
    const float* b_m2   = (const float*)d_in[14];
    float* out = (float*)d_out;

    float *p_h, *p_ab, *p_abr, *p_conv, *p_gates, *p_gx, *p_x2, *p_m, *p_mi;
    float *p_wk, *p_wlin1, *p_wrg, *p_wout, *p_wm1, *p_wm2;
    cudaGetSymbolAddress((void**)&p_h, g_h);
    cudaGetSymbolAddress((void**)&p_ab, g_ab);
    cudaGetSymbolAddress((void**)&p_abr, g_abr);
    cudaGetSymbolAddress((void**)&p_conv, g_conv);
    cudaGetSymbolAddress((void**)&p_gates, g_gates);
    cudaGetSymbolAddress((void**)&p_gx, g_gx);
    cudaGetSymbolAddress((void**)&p_x2, g_x2);
    cudaGetSymbolAddress((void**)&p_m, g_m);
    cudaGetSymbolAddress((void**)&p_mi, g_mi);
    cudaGetSymbolAddress((void**)&p_wk, g_wk);
    cudaGetSymbolAddress((void**)&p_wlin1, g_wlin1);
    cudaGetSymbolAddress((void**)&p_wrg, g_wrg);
    cudaGetSymbolAddress((void**)&p_wout, g_wout);
    cudaGetSymbolAddress((void**)&p_wm1, g_wm1);
    cudaGetSymbolAddress((void**)&p_wm2, g_wm2);

    cudaFuncSetAttribute(tc_gemm<0>, cudaFuncAttributeMaxDynamicSharedMemorySize, SMEM_BYTES);
    cudaFuncSetAttribute(tc_gemm<1>, cudaFuncAttributeMaxDynamicSharedMemorySize, SMEM_BYTES);
    cudaFuncSetAttribute(tc_gemm<2>, cudaFuncAttributeMaxDynamicSharedMemorySize, SMEM_BYTES);
    cudaFuncSetAttribute(tc_gemm<3>, cudaFuncAttributeMaxDynamicSharedMemorySize, SMEM_BYTES);
    cudaFuncSetAttribute(tc_gemm<4>, cudaFuncAttributeMaxDynamicSharedMemorySize, SMEM_BYTES);

    // 0) tf32-round all weights (unbiased RNA rounding; avoids HW RZ-truncation bias)
    cvt_copy_k<<<(2 * DR * DM / 4 + 255) / 256, 256>>>(w_lin1, p_wlin1, 2 * DR * DM);
    cvt_copy_k<<<(2 * DR * DR / 4 + 255) / 256, 256>>>(w_rg, p_wrg, 2 * DR * DR);
    cvt_copy_k<<<(DM * DR / 4 + 255) / 256, 256>>>(w_out, p_wout, DM * DR);
    cvt_copy_k<<<(2 * MI * DM / 4 + 255) / 256, 256>>>(w_m1, p_wm1, 2 * MI * DM);
    cvt_copy_k<<<(DM * MI / 4 + 255) / 256, 256>>>(w_m2, p_wm2, DM * MI);
    repack_wconv_k<<<(DR * 4 * DR + 255) / 256, 256>>>(w_conv);

    // 1) h = rmsnorm(x, w_n1)
    rmsnorm_k<<<S, 256>>>(x, w_n1, p_h, DM);
    // 2) ab = h @ w_lin1^T + b_lin1 ; a_branch = gelu fused; C rounded (b_branch feeds conv)
    tc_gemm<4><<<dim3(2 * DR / 128, S / 128), 256, SMEM_BYTES>>>(
        p_h, DM, p_wlin1, b_lin1, nullptr, p_ab, 2 * DR, p_abr, DM, 0);
    // 3) conv = causal conv as single K=4096 GEMM (shifted A rows, zfill for t<0)
    tc_gemm<0><<<dim3(DR / 128, S / 128), 256, SMEM_BYTES>>>(
        p_ab + DR, 2 * DR, p_wk, nullptr, nullptr, p_conv, DR, nullptr, 4 * DR, 1);
    // 4) gates = sigmoid(conv @ w_rg^T + b_rg)
    tc_gemm<2><<<dim3(2 * DR / 128, S / 128), 256, SMEM_BYTES>>>(
        p_conv, DR, p_wrg, b_rg, nullptr, p_gates, 2 * DR, nullptr, DR, 0);
    // 5) a, gated_x
    gates_proc_k<<<(S * DR + 255) / 256, 256>>>(Lambda);
    // 6) linear recurrence scan
    scan_pass1_k<<<dim3(NCHUNK, DR / 256), 256>>>();
    scan_pass2_k<<<DR / 256, 256>>>();
    scan_pass3_k<<<dim3(NCHUNK, DR / 256), 256>>>();
    // 7) ya = a_branch * y (into g_gx, tf32-rounded)
    ya_k<<<(S * DR + 255) / 256, 256>>>();
    // 8) x2 = x + ya @ w_out^T + b_out   (fp32 residual path)
    tc_gemm<3><<<dim3(DM / 128, S / 128), 256, SMEM_BYTES>>>(
        p_gx, DR, p_wout, b_out, x, p_x2, DM, nullptr, DR, 0);
    // 9) h2 = rmsnorm(x2, w_n2)
    rmsnorm_k<<<S, 256>>>(p_x2, w_n2, p_h, DM);
    // 10) m = h2 @ w_m1^T + b_m1
    tc_gemm<1><<<dim3(2 * MI / 128, S / 128), 256, SMEM_BYTES>>>(
        p_h, DM, p_wm1, b_m1, nullptr, p_m, 2 * MI, nullptr, DM, 0);
    // 11) mi = gelu(m[:, :MI]) * m[:, MI:]  (tf32-rounded)
    glu_k<<<(S * MI + 255) / 256, 256>>>();
    // 12) out = x2 + mi @ w_m2^T + b_m2   (fp32 residual path)
    tc_gemm<3><<<dim3(DM / 128, S / 128), 256, SMEM_BYTES>>>(
        p_mi, MI, p_wm2, b_m2, p_x2, out, DM, nullptr, MI, 0);
}

// round 11
// speedup vs baseline: 3.5487x; 1.0270x over previous
#include <cuda_runtime.h>
#include <cuda_fp16.h>
#include <math.h>
#include <stdint.h>

#define S 8192
#define DM 768
#define DR 1024
#define MI 3072

// ------------------- scratch (device globals; no allocs allowed) -------------------
__device__ __half g_hh[S * DM];          // rmsnorm output (h, then h2), fp16
__device__ __half g_abr[S * DR];         // gelu(a_branch), fp16
__device__ __half g_bb[S * DR];          // b_branch, fp16
__device__ float  g_conv[S * DR];        // conv output fp32 (for gx math)
__device__ __half g_convh[S * DR];       // conv output fp16 (gates GEMM operand)
__device__ float  g_a[S * DR];           // recurrence decay
__device__ float  g_gx[S * DR];          // gated_x
__device__ __half g_ya[S * DR];          // a_branch * y, fp16 (out-GEMM operand)
__device__ float  g_x2[S * DM];          // x + tempmix
__device__ __half g_mi[S * MI];          // GLU output, fp16 (m2-GEMM operand)
// fp16 weights (converted once per launch; *_i = row-interleaved pairs)
__device__ __half g_wlin1i[2 * DR * DM];
__device__ __half g_wk[DR * 4 * DR];     // conv repacked [N=1024][K=4096]
__device__ __half g_wrgi[2 * DR * DR];
__device__ __half g_wout[DM * DR];
__device__ __half g_wm1i[2 * MI * DM];
__device__ __half g_wm2[DM * MI];
#define NCHUNK 64
#define SCHUNK 128
__device__ float g_Ag[NCHUNK * DR];
__device__ float g_Bg[NCHUNK * DR];
__device__ float g_carry[NCHUNK * DR];

// ------------------- math helpers -------------------
__device__ __forceinline__ float gelu_f(float x) {
    float x3 = x * x * x;
    return 0.5f * x * (1.0f + tanhf(0.7978845608028654f * (x + 0.044715f * x3)));
}
__device__ __forceinline__ float sigmoid_f(float x) { return 1.0f / (1.0f + expf(-x)); }

// ------------------- cp.async helpers -------------------
__device__ __forceinline__ uint32_t smem_u32(const void* p) {
    uint32_t a;
    asm("{ .reg .u64 t; cvta.to.shared.u64 t, %1; cvt.u32.u64 %0, t; }" : "=r"(a) : "l"(p));
    return a;
}
#define CP16(dst, src) \
    asm volatile("cp.async.cg.shared.global [%0], [%1], 16;" :: "r"(dst), "l"(src))
#define CP16_ZFILL(dst, src) \
    asm volatile("cp.async.cg.shared.global [%0], [%1], 16, 0;" :: "r"(dst), "l"(src))
#define CP_COMMIT() asm volatile("cp.async.commit_group;" ::: "memory")
#define CP_WAIT(n) asm volatile("cp.async.wait_group %0;" :: "n"(n) : "memory")

// ------------------- fp16 mma.sync m16n8k16 (fp32 accum) -------------------
__device__ __forceinline__ void mma_f16(float* c, const uint32_t* a, const uint32_t* b) {
    asm volatile(
        "mma.sync.aligned.m16n8k16.row.col.f32.f16.f16.f32 "
        "{%0,%1,%2,%3}, {%4,%5,%6,%7}, {%8,%9}, {%0,%1,%2,%3};"
        : "+f"(c[0]), "+f"(c[1]), "+f"(c[2]), "+f"(c[3])
        : "r"(a[0]), "r"(a[1]), "r"(a[2]), "r"(a[3]), "r"(b[0]), "r"(b[1]));
}

// ------------------- fp16 GEMM: C[M,N] = A[M,K] @ W[N,K]^T (+fused epilogues) ------
// Tile 128x128x64, 3-stage cp.async, 256 threads (2x4 warps), warp tile 64x32.
// EPI 0: conv      -> C fp32 + Cb fp16
// EPI 2: gates     -> pairwise (ig,rg): a=exp(-8 sp(lam) rg), gx=sqrt(1-a^2) ig conv; C=g_a, C2=g_gx
// EPI 3: +bias+res -> C fp32 (out / m2)
// EPI 4: lin1      -> pairwise: Cb2=gelu(a+bias) fp16, Cb=b+bias fp16
// EPI 5: m1+GLU    -> pairwise: Cb=gelu(u)*v fp16
#define STAGES 3
#define BK 64
#define SK 72                         // padded row stride in halves (64+8 -> 144B)
#define ASTG (128 * SK)               // halves per operand per stage

template <int EPI>
__global__ void __launch_bounds__(256, 2)
tc_gemm(const __half* __restrict__ A, int lda, const __half* __restrict__ W,
        const float* __restrict__ bias, const float* __restrict__ res,
        float* __restrict__ C, int ldc, float* __restrict__ C2,
        __half* __restrict__ Cb, __half* __restrict__ Cb2,
        const float* __restrict__ aux, const float* __restrict__ lam,
        int K, int shifted) {
    extern __shared__ __half sm[];
    __half* sA = sm;
    __half* sB = sm + STAGES * ASTG;
    const int tid = threadIdx.x, lane = tid & 31, wid = tid >> 5;
    const int wm = wid & 1, wn = wid >> 1, laneg = lane >> 2, lanet = lane & 3;
    const int bm = blockIdx.y * 128, bn = blockIdx.x * 128;
    const int ktiles = K >> 6;
    const uint32_t sAaddr = smem_u32(sA), sBaddr = smem_u32(sB);

    float acc[4][4][4];
#pragma unroll
    for (int i = 0; i < 4; i++)
#pragma unroll
        for (int j = 0; j < 4; j++)
#pragma unroll
            for (int t = 0; t < 4; t++) acc[i][j][t] = 0.f;

    auto load_stage = [&](int kt, int st) {
#pragma unroll
        for (int i = 0; i < 4; i++) {                 // A: 1024 16B chunks (128 rows x 64 halves)
            int c = tid + 256 * i;
            int row = c >> 3, kc = c & 7;
            int grow, gcol;
            if (shifted) { int seg = kt >> 4; grow = bm + row + seg - 3; gcol = ((kt & 15) << 6) + (kc << 3); }
            else { grow = bm + row; gcol = (kt << 6) + (kc << 3); }
            uint32_t dst = sAaddr + (uint32_t)(st * ASTG + row * SK + (kc << 3)) * 2u;
            const __half* src = A + (size_t)grow * lda + gcol;
            if (shifted && grow < 0) CP16_ZFILL(dst, A);
            else CP16(dst, src);
        }
#pragma unroll
        for (int i = 0; i < 4; i++) {                 // B
            int c = tid + 256 * i;
            int row = c >> 3, kc = c & 7;
            uint32_t dst = sBaddr + (uint32_t)(st * ASTG + row * SK + (kc << 3)) * 2u;
            const __half* src = W + (size_t)(bn + row) * K + (kt << 6) + (kc << 3);
            CP16(dst, src);
        }
    };

    auto compute_stage = [&](int st) {
        const uint32_t* a32 = (const uint32_t*)(sA + st * ASTG);
        const uint32_t* b32 = (const uint32_t*)(sB + st * ASTG);
#pragma unroll
        for (int k16 = 0; k16 < 4; k16++) {
            int k0 = k16 * 16;
            uint32_t af[4][4], bf[4][2];
#pragma unroll
            for (int mf = 0; mf < 4; mf++) {
                int r = (wm * 64 + mf * 16 + laneg) * SK + k0 + 2 * lanet;  // half idx, even
                af[mf][0] = a32[r >> 1];
                af[mf][1] = a32[(r + 8 * SK) >> 1];
                af[mf][2] = a32[(r + 8) >> 1];
                af[mf][3] = a32[(r + 8 * SK + 8) >> 1];
            }
#pragma unroll
            for (int nf = 0; nf < 4; nf++) {
                int r = (wn * 32 + nf * 8 + laneg) * SK + k0 + 2 * lanet;
                bf[nf][0] = b32[r >> 1];
                bf[nf][1] = b32[(r + 8) >> 1];
            }
#pragma unroll
            for (int mf = 0; mf < 4; mf++)
#pragma unroll
                for (int nf = 0; nf < 4; nf++) mma_f16(acc[mf][nf], af[mf], bf[nf]);
        }
    };

#pragma unroll
    for (int s = 0; s < STAGES - 1; s++) { load_stage(s, s); CP_COMMIT(); }
    for (int kt = 0; kt < ktiles; kt++) {
        CP_WAIT(1);
        __syncthreads();
        int nk = kt + STAGES - 1;
        if (nk < ktiles) load_stage(nk, nk % STAGES);
        CP_COMMIT();
        compute_stage(kt % STAGES);
    }
    CP_WAIT(0);

    // ---------------- epilogues ----------------
    if (EPI == 0 || EPI == 3) {
#pragma unroll
        for (int mf = 0; mf < 4; mf++)
#pragma unroll
            for (int half = 0; half < 2; half++) {
                int row = bm + wm * 64 + mf * 16 + laneg + half * 8;
                size_t crow = (size_t)row * ldc;
#pragma unroll
                for (int nf = 0; nf < 4; nf++) {
                    int col = bn + wn * 32 + nf * 8 + lanet * 2;
                    float v0 = acc[mf][nf][half * 2];
                    float v1 = acc[mf][nf][half * 2 + 1];
                    if (EPI == 3) {
                        v0 += bias[col] + res[crow + col];
                        v1 += bias[col + 1] + res[crow + col + 1];
                    }
                    *(float2*)&C[crow + col] = make_float2(v0, v1);
                    if (EPI == 0) {
                        __half2 hv; hv.x = __float2half(v0); hv.y = __float2half(v1);
                        *(__half2*)&Cb[crow + col] = hv;
                    }
                }
            }
    } else {  // pairwise EPIs: thread holds (2c, 2c+1)
#pragma unroll
        for (int nf = 0; nf < 4; nf++) {
            int c = (bn + wn * 32 + nf * 8 + lanet * 2) >> 1;
            float sp, b0, b1;
            if (EPI == 2) { sp = log1pf(expf(lam[c])); b0 = bias[c]; b1 = bias[DR + c]; }
            if (EPI == 4) { b0 = bias[c]; b1 = bias[DR + c]; }
            if (EPI == 5) { b0 = bias[c]; b1 = bias[MI + c]; }
#pragma unroll
            for (int mf = 0; mf < 4; mf++)
#pragma unroll
                for (int half = 0; half < 2; half++) {
                    int row = bm + wm * 64 + mf * 16 + laneg + half * 8;
                    float v0 = acc[mf][nf][half * 2] + b0;
                    float v1 = acc[mf][nf][half * 2 + 1] + b1;
                    if (EPI == 2) {
                        float ig = sigmoid_f(v0), rg = sigmoid_f(v1);
                        float a = expf(-8.0f * sp * rg);
                        float gx = sqrtf(fmaxf(1.0f - a * a, 0.f)) * ig * aux[(size_t)row * DR + c];
                        C[(size_t)row * DR + c] = a;
                        C2[(size_t)row * DR + c] = gx;
                    } else if (EPI == 4) {
                        Cb2[(size_t)row * DR + c] = __float2half(gelu_f(v0));
                        Cb[(size_t)row * DR + c] = __float2half(v1);
                    } else {  // EPI 5
                        Cb[(size_t)row * MI + c] = __float2half(gelu_f(v0) * v1);
                    }
                }
        }
    }
}

// ------------------- RMSNorm (fp16 output: feeds GEMMs) -------------------
__global__ __launch_bounds__(256) void rmsnorm_k(const float* __restrict__ x,
                                                 const float* __restrict__ w,
                                                 __half* __restrict__ o, int D) {
    int row = blockIdx.x;
    const float* xr = x + (size_t)row * D;
    float s = 0.f;
    for (int i = threadIdx.x; i < D; i += 256) { float v = xr[i]; s += v * v; }
    __shared__ float sm[8];
    __shared__ float s_inv;
    for (int off = 16; off; off >>= 1) s += __shfl_down_sync(0xffffffffu, s, off);
    if ((threadIdx.x & 31) == 0) sm[threadIdx.x >> 5] = s;
    __syncthreads();
    if (threadIdx.x == 0) {
        float t = 0.f;
#pragma unroll
        for (int i = 0; i < 8; i++) t += sm[i];
        s_inv = rsqrtf(t / (float)D + 1e-5f);
    }
    __syncthreads();
    float inv = s_inv;
    __half* orow = o + (size_t)row * D;
    for (int i = threadIdx.x; i < D; i += 256) orow[i] = __float2half(xr[i] * inv * w[i]);
}

// ------------------- weight conversion kernels -------------------
__global__ __launch_bounds__(256) void cvt_w_k(const float* __restrict__ src,
                                               __half* __restrict__ dst, int n) {
    int i = (blockIdx.x * 256 + threadIdx.x) * 4;
    if (i >= n) return;
    float4 v = *(const float4*)(src + i);
    __half2 h0; h0.x = __float2half(v.x); h0.y = __float2half(v.y);
    __half2 h1; h1.x = __float2half(v.z); h1.y = __float2half(v.w);
    *(__half2*)(dst + i) = h0;
    *(__half2*)(dst + i + 2) = h1;
}
// interleave rows: dst[2c+p][k] = src[p*Nh + c][k]
__global__ __launch_bounds__(256) void cvt_w_pair_k(const float* __restrict__ src,
                                                    __half* __restrict__ dst, int Nh, int K) {
    int i = blockIdx.x * 256 + threadIdx.x;
    if (i >= 2 * Nh * K) return;
    int n = i / K, k = i - n * K;
    int c = n >> 1, p = n & 1;
    dst[i] = __float2half(src[(size_t)(p * Nh + c) * K + k]);
}
__global__ __launch_bounds__(256) void repack_wconv_k(const float* __restrict__ w_conv) {
    int i = blockIdx.x * 256 + threadIdx.x;
    if (i >= DR * 4 * DR) return;
    int n = i >> 12;
    int rem = i & 4095;
    int t = rem >> 10;
    int kin = rem & 1023;
    g_wk[i] = __float2half(w_conv[((size_t)n << 12) + (kin << 2) + t]);
}

// ------------------- chunked linear-recurrence scan -------------------
__global__ __launch_bounds__(256) void scan_pass1_k() {
    int c = blockIdx.y * 256 + threadIdx.x;
    int j = blockIdx.x;
    size_t base = (size_t)j * SCHUNK * DR + c;
    float A = 1.f, B = 0.f;
#pragma unroll 4
    for (int t = 0; t < SCHUNK; t++) {
        float at = g_a[base + (size_t)t * DR];
        float gx = g_gx[base + (size_t)t * DR];
        B = fmaf(at, B, gx);
        A *= at;
    }
    g_Ag[j * DR + c] = A;
    g_Bg[j * DR + c] = B;
}
__global__ __launch_bounds__(256) void scan_pass2_k() {
    int c = blockIdx.x * 256 + threadIdx.x;
    float h = 0.f;
    for (int j = 0; j < NCHUNK; j++) {
        g_carry[j * DR + c] = h;
        h = fmaf(g_Ag[j * DR + c], h, g_Bg[j * DR + c]);
    }
}
// pass3 fused with ya = a_branch * y, fp16 store
__global__ __launch_bounds__(256) void scan_pass3_k() {
    int c = blockIdx.y * 256 + threadIdx.x;
    int j = blockIdx.x;
    size_t base = (size_t)j * SCHUNK * DR + c;
    float h = g_carry[j * DR + c];
#pragma unroll 4
    for (int t = 0; t < SCHUNK; t++) {
        float at = g_a[base + (size_t)t * DR];
        float gx = g_gx[base + (size_t)t * DR];
        h = fmaf(at, h, gx);
        g_ya[base + (size_t)t * DR] = __float2half(h * __half2float(g_abr[base + (size_t)t * DR]));
    }
}

// ------------------- launch -------------------
#define SMEM_BYTES (STAGES * ASTG * 2 * 2)

extern "C" void kernel_launch(void* const* d_in, const int* in_sizes, int n_in,
                              void* d_out, int out_size) {
    const float* x      = (const float*)d_in[0];
    const float* w_n1   = (const float*)d_in[1];
    const float* w_n2   = (const float*)d_in[2];
    const float* w_lin1 = (const float*)d_in[3];
    const float* b_lin1 = (const float*)d_in[4];
    const float* w_conv = (const float*)d_in[5];
    const float* w_rg   = (const float*)d_in[6];
    const float* b_rg   = (const float*)d_in[7];
    const float* Lambda = (const float*)d_in[8];
    const float* w_out  = (const float*)d_in[9];
    const float* b_out  = (const float*)d_in[10];
    const float* w_m1   = (const float*)d_in[11];
    const float* b_m1   = (const float*)d_in[12];
    const float* w_m2   = (const float*)d_in[13];
    const float* b_m2   = (const float*)d_in[14];
    float* out = (float*)d_out;

    __half *p_hh, *p_abr, *p_bb, *p_convh, *p_ya, *p_mi;
    __half *p_wlin1i, *p_wrgi, *p_wout, *p_wm1i, *p_wm2, *p_wk;
    float *p_conv, *p_a, *p_gx, *p_x2;
    cudaGetSymbolAddress((void**)&p_hh, g_hh);
    cudaGetSymbolAddress((void**)&p_abr, g_abr);
    cudaGetSymbolAddress((void**)&p_bb, g_bb);
    cudaGetSymbolAddress((void**)&p_conv, g_conv);
    cudaGetSymbolAddress((void**)&p_convh, g_convh);
    cudaGetSymbolAddress((void**)&p_a, g_a);
    cudaGetSymbolAddress((void**)&p_gx, g_gx);
    cudaGetSymbolAddress((void**)&p_ya, g_ya);
    cudaGetSymbolAddress((void**)&p_x2, g_x2);
    cudaGetSymbolAddress((void**)&p_mi, g_mi);
    cudaGetSymbolAddress((void**)&p_wlin1i, g_wlin1i);
    cudaGetSymbolAddress((void**)&p_wrgi, g_wrgi);
    cudaGetSymbolAddress((void**)&p_wout, g_wout);
    cudaGetSymbolAddress((void**)&p_wm1i, g_wm1i);
    cudaGetSymbolAddress((void**)&p_wm2, g_wm2);
    cudaGetSymbolAddress((void**)&p_wk, g_wk);    // <-- R10 bug: was passing symbol directly

    cudaFuncSetAttribute(tc_gemm<0>, cudaFuncAttributeMaxDynamicSharedMemorySize, SMEM_BYTES);
    cudaFuncSetAttribute(tc_gemm<2>, cudaFuncAttributeMaxDynamicSharedMemorySize, SMEM_BYTES);
    cudaFuncSetAttribute(tc_gemm<3>, cudaFuncAttributeMaxDynamicSharedMemorySize, SMEM_BYTES);
    cudaFuncSetAttribute(tc_gemm<4>, cudaFuncAttributeMaxDynamicSharedMemorySize, SMEM_BYTES);
    cudaFuncSetAttribute(tc_gemm<5>, cudaFuncAttributeMaxDynamicSharedMemorySize, SMEM_BYTES);

    // 0) convert weights to fp16 (interleaved where the epilogue pairs columns)
    cvt_w_pair_k<<<(2 * DR * DM + 255) / 256, 256>>>(w_lin1, p_wlin1i, DR, DM);
    cvt_w_pair_k<<<(2 * DR * DR + 255) / 256, 256>>>(w_rg, p_wrgi, DR, DR);
    cvt_w_pair_k<<<(2 * MI * DM + 255) / 256, 256>>>(w_m1, p_wm1i, MI, DM);
    cvt_w_k<<<(DM * DR / 4 + 255) / 256, 256>>>(w_out, p_wout, DM * DR);
    cvt_w_k<<<(DM * MI / 4 + 255) / 256, 256>>>(w_m2, p_wm2, DM * MI);
    repack_wconv_k<<<(DR * 4 * DR + 255) / 256, 256>>>(w_conv);

    // 1) h = rmsnorm(x, w_n1) -> fp16
    rmsnorm_k<<<S, 256>>>(x, w_n1, p_hh, DM);
    // 2) lin1 (interleaved): abr = gelu(a+b), bb = b_branch, both fp16
    tc_gemm<4><<<dim3(2 * DR / 128, S / 128), 256, SMEM_BYTES>>>(
        p_hh, DM, p_wlin1i, b_lin1, nullptr, nullptr, DR, nullptr, p_bb, p_abr,
        nullptr, nullptr, DM, 0);
    // 3) conv = causal conv as K=4096 GEMM (shifted A rows, zfill t<0) -> fp32 + fp16
    tc_gemm<0><<<dim3(DR / 128, S / 128), 256, SMEM_BYTES>>>(
        p_bb, DR, p_wk, nullptr, nullptr, p_conv, DR, nullptr, p_convh, nullptr,
        nullptr, nullptr, 4 * DR, 1);
    // 4) gates GEMM (interleaved) with fused a/gated_x epilogue
    tc_gemm<2><<<dim3(2 * DR / 128, S / 128), 256, SMEM_BYTES>>>(
        p_convh, DR, p_wrgi, b_rg, nullptr, p_a, DR, p_gx, nullptr, nullptr,
        p_conv, Lambda, DR, 0);
    // 5) linear recurrence scan (pass3 fused with ya = abr*y -> fp16)
    scan_pass1_k<<<dim3(NCHUNK, DR / 256), 256>>>();
    scan_pass2_k<<<DR / 256, 256>>>();
    scan_pass3_k<<<dim3(NCHUNK, DR / 256), 256>>>();
    // 6) x2 = x + ya @ w_out^T + b_out   (fp32 residual path)
    tc_gemm<3><<<dim3(DM / 128, S / 128), 256, SMEM_BYTES>>>(
        p_ya, DR, p_wout, b_out, x, p_x2, DM, nullptr, nullptr, nullptr,
        nullptr, nullptr, DR, 0);
    // 7) h2 = rmsnorm(x2, w_n2) -> fp16
    rmsnorm_k<<<S, 256>>>(p_x2, w_n2, p_hh, DM);
    // 8) m1 (interleaved) with fused GLU: mi = gelu(u)*v -> fp16
    tc_gemm<5><<<dim3(2 * MI / 128, S / 128), 256, SMEM_BYTES>>>(
        p_hh, DM, p_wm1i, b_m1, nullptr, nullptr, MI, nullptr, p_mi, nullptr,
        nullptr, nullptr, DM, 0);
    // 9) out = x2 + mi @ w_m2^T + b_m2   (fp32 residual path)
    tc_gemm<3><<<dim3(DM / 128, S / 128), 256, SMEM_BYTES>>>(
        p_mi, MI, p_wm2, b_m2, p_x2, out, DM, nullptr, nullptr, nullptr,
        nullptr, nullptr, MI, 0);
}

// round 12
// speedup vs baseline: 6.2434x; 1.7593x over previous
#include <cuda_runtime.h>
#include <cuda_fp16.h>
#include <math.h>
#include <stdint.h>

#define S 8192
#define DM 768
#define DR 1024
#define MI 3072

// ------------------- scratch (device globals; no allocs allowed) -------------------
__device__ __half g_hh[S * DM];          // rmsnorm output (h, then h2), fp16
__device__ __half g_abr[S * DR];         // gelu(a_branch), fp16
__device__ __half g_bb[S * DR];          // b_branch, fp16
__device__ float  g_conv[S * DR];        // conv output fp32 (for gx math)
__device__ __half g_convh[S * DR];       // conv output fp16 (gates GEMM operand)
__device__ float  g_a[S * DR];           // recurrence decay
__device__ float  g_gx[S * DR];          // gated_x
__device__ __half g_ya[S * DR];          // a_branch * y, fp16 (out-GEMM operand)
__device__ float  g_x2[S * DM];          // x + tempmix
__device__ __half g_mi[S * MI];          // GLU output, fp16 (m2-GEMM operand)
// fp16 weights (converted once per launch; *_i = row-interleaved pairs)
__device__ __half g_wlin1i[2 * DR * DM];
__device__ __half g_wk[DR * 4 * DR];     // conv repacked [N=1024][K=4096]
__device__ __half g_wrgi[2 * DR * DR];
__device__ __half g_wout[DM * DR];
__device__ __half g_wm1i[2 * MI * DM];
__device__ __half g_wm2[DM * MI];
#define NCHUNK 64
#define SCHUNK 128
__device__ float g_Ag[NCHUNK * DR];
__device__ float g_Bg[NCHUNK * DR];
__device__ float g_carry[NCHUNK * DR];

// ------------------- math helpers -------------------
__device__ __forceinline__ float gelu_f(float x) {
    float x3 = x * x * x;
    return 0.5f * x * (1.0f + tanhf(0.7978845608028654f * (x + 0.044715f * x3)));
}
__device__ __forceinline__ float sigmoid_f(float x) { return 1.0f / (1.0f + expf(-x)); }

// ------------------- cp.async / ldmatrix helpers -------------------
__device__ __forceinline__ uint32_t smem_u32(const void* p) {
    uint32_t a;
    asm("{ .reg .u64 t; cvta.to.shared.u64 t, %1; cvt.u32.u64 %0, t; }" : "=r"(a) : "l"(p));
    return a;
}
#define CP16(dst, src) \
    asm volatile("cp.async.cg.shared.global [%0], [%1], 16;" :: "r"(dst), "l"(src))
#define CP16_ZFILL(dst, src) \
    asm volatile("cp.async.cg.shared.global [%0], [%1], 16, 0;" :: "r"(dst), "l"(src))
#define CP_COMMIT() asm volatile("cp.async.commit_group;" ::: "memory")
#define CP_WAIT(n) asm volatile("cp.async.wait_group %0;" :: "n"(n) : "memory")
#define LDSM_X4(r0, r1, r2, r3, addr)                                           \
    asm volatile("ldmatrix.sync.aligned.m8n8.x4.shared.b16 {%0,%1,%2,%3}, [%4];" \
                 : "=r"(r0), "=r"(r1), "=r"(r2), "=r"(r3) : "r"(addr))

// ------------------- fp16 mma.sync m16n8k16 (fp32 accum) -------------------
__device__ __forceinline__ void mma_f16(float* c, const uint32_t* a, const uint32_t* b) {
    asm volatile(
        "mma.sync.aligned.m16n8k16.row.col.f32.f16.f16.f32 "
        "{%0,%1,%2,%3}, {%4,%5,%6,%7}, {%8,%9}, {%0,%1,%2,%3};"
        : "+f"(c[0]), "+f"(c[1]), "+f"(c[2]), "+f"(c[3])
        : "r"(a[0]), "r"(a[1]), "r"(a[2]), "r"(a[3]), "r"(b[0]), "r"(b[1]));
}

// ------------------- fp16 GEMM: C[M,N] = A[M,K] @ W[N,K]^T (+fused epilogues) ------
// Tile 128x128x64, 3-stage cp.async, 256 threads (2x4 warps), warp tile 64x32.
// Operand fetch via ldmatrix.x4 (conflict-free on SK=72 padded rows).
// EPI 0: conv      -> C fp32 + Cb fp16
// EPI 2: gates     -> pairwise (ig,rg): a=exp(-8 sp(lam) rg), gx=sqrt(1-a^2) ig conv
// EPI 3: +bias+res -> C fp32 (out / m2)
// EPI 4: lin1      -> pairwise: Cb2=gelu(a+bias) fp16, Cb=b+bias fp16
// EPI 5: m1+GLU    -> pairwise: Cb=gelu(u)*v fp16
#define STAGES 3
#define BK 64
#define SK 72                         // padded row stride in halves (64+8 -> 144B)
#define ASTG (128 * SK)               // halves per operand per stage

template <int EPI>
__global__ void __launch_bounds__(256, 2)
tc_gemm(const __half* __restrict__ A, int lda, const __half* __restrict__ W,
        const float* __restrict__ bias, const float* __restrict__ res,
        float* __restrict__ C, int ldc, float* __restrict__ C2,
        __half* __restrict__ Cb, __half* __restrict__ Cb2,
        const float* __restrict__ aux, const float* __restrict__ lam,
        int K, int shifted) {
    extern __shared__ __half sm[];
    __half* sA = sm;
    __half* sB = sm + STAGES * ASTG;
    const int tid = threadIdx.x, lane = tid & 31, wid = tid >> 5;
    const int wm = wid & 1, wn = wid >> 1, laneg = lane >> 2, lanet = lane & 3;
    const int bm = blockIdx.y * 128, bn = blockIdx.x * 128;
    const int ktiles = K >> 6;
    const uint32_t sAaddr = smem_u32(sA), sBaddr = smem_u32(sB);

    // ldmatrix lane-address bases (bytes), before stage/k/frag offsets
    const uint32_t aBase = sAaddr +
        (uint32_t)((wm * 64 + (lane & 15)) * SK + ((lane >> 4) << 3)) * 2u;
    const uint32_t bBase = sBaddr +
        (uint32_t)((wn * 32 + (lane & 7) + (((lane >> 4) & 1) << 3)) * SK +
                   (((lane >> 3) & 1) << 3)) * 2u;

    float acc[4][4][4];
#pragma unroll
    for (int i = 0; i < 4; i++)
#pragma unroll
        for (int j = 0; j < 4; j++)
#pragma unroll
            for (int t = 0; t < 4; t++) acc[i][j][t] = 0.f;

    auto load_stage = [&](int kt, int st) {
#pragma unroll
        for (int i = 0; i < 4; i++) {                 // A: 1024 16B chunks (128 rows x 64 halves)
            int c = tid + 256 * i;
            int row = c >> 3, kc = c & 7;
            int grow, gcol;
            if (shifted) { int seg = kt >> 4; grow = bm + row + seg - 3; gcol = ((kt & 15) << 6) + (kc << 3); }
            else { grow = bm + row; gcol = (kt << 6) + (kc << 3); }
            uint32_t dst = sAaddr + (uint32_t)(st * ASTG + row * SK + (kc << 3)) * 2u;
            const __half* src = A + (size_t)grow * lda + gcol;
            if (shifted && grow < 0) CP16_ZFILL(dst, A);
            else CP16(dst, src);
        }
#pragma unroll
        for (int i = 0; i < 4; i++) {                 // B
            int c = tid + 256 * i;
            int row = c >> 3, kc = c & 7;
            uint32_t dst = sBaddr + (uint32_t)(st * ASTG + row * SK + (kc << 3)) * 2u;
            const __half* src = W + (size_t)(bn + row) * K + (kt << 6) + (kc << 3);
            CP16(dst, src);
        }
    };

    auto compute_stage = [&](int st) {
        const uint32_t stoff = (uint32_t)(st * ASTG) * 2u;
#pragma unroll
        for (int k16 = 0; k16 < 4; k16++) {
            const uint32_t kb = (uint32_t)(k16 * 16) * 2u;
            uint32_t af[4][4], bf[4][2];
#pragma unroll
            for (int mf = 0; mf < 4; mf++) {
                uint32_t addr = aBase + stoff + (uint32_t)(mf * 16 * SK) * 2u + kb;
                LDSM_X4(af[mf][0], af[mf][1], af[mf][2], af[mf][3], addr);
            }
#pragma unroll
            for (int np = 0; np < 2; np++) {
                uint32_t addr = bBase + stoff + (uint32_t)(np * 16 * SK) * 2u + kb;
                LDSM_X4(bf[2 * np][0], bf[2 * np][1], bf[2 * np + 1][0], bf[2 * np + 1][1], addr);
            }
#pragma unroll
            for (int mf = 0; mf < 4; mf++)
#pragma unroll
                for (int nf = 0; nf < 4; nf++) mma_f16(acc[mf][nf], af[mf], bf[nf]);
        }
    };

#pragma unroll
    for (int s = 0; s < STAGES - 1; s++) { load_stage(s, s); CP_COMMIT(); }
    for (int kt = 0; kt < ktiles; kt++) {
        CP_WAIT(1);
        __syncthreads();
        int nk = kt + STAGES - 1;
        if (nk < ktiles) load_stage(nk, nk % STAGES);
        CP_COMMIT();
        compute_stage(kt % STAGES);
    }
    CP_WAIT(0);

    // ---------------- epilogues ----------------
    if (EPI == 0 || EPI == 3) {
#pragma unroll
        for (int mf = 0; mf < 4; mf++)
#pragma unroll
            for (int half = 0; half < 2; half++) {
                int row = bm + wm * 64 + mf * 16 + laneg + half * 8;
                size_t crow = (size_t)row * ldc;
#pragma unroll
                for (int nf = 0; nf < 4; nf++) {
                    int col = bn + wn * 32 + nf * 8 + lanet * 2;
                    float v0 = acc[mf][nf][half * 2];
                    float v1 = acc[mf][nf][half * 2 + 1];
                    if (EPI == 3) {
                        v0 += bias[col] + res[crow + col];
                        v1 += bias[col + 1] + res[crow + col + 1];
                    }
                    *(float2*)&C[crow + col] = make_float2(v0, v1);
                    if (EPI == 0) {
                        __half2 hv; hv.x = __float2half(v0); hv.y = __float2half(v1);
                        *(__half2*)&Cb[crow + col] = hv;
                    }
                }
            }
    } else {  // pairwise EPIs: thread holds (2c, 2c+1)
#pragma unroll
        for (int nf = 0; nf < 4; nf++) {
            int c = (bn + wn * 32 + nf * 8 + lanet * 2) >> 1;
            float sp, b0, b1;
            if (EPI == 2) { sp = log1pf(expf(lam[c])); b0 = bias[c]; b1 = bias[DR + c]; }
            if (EPI == 4) { b0 = bias[c]; b1 = bias[DR + c]; }
            if (EPI == 5) { b0 = bias[c]; b1 = bias[MI + c]; }
#pragma unroll
            for (int mf = 0; mf < 4; mf++)
#pragma unroll
                for (int half = 0; half < 2; half++) {
                    int row = bm + wm * 64 + mf * 16 + laneg + half * 8;
                    float v0 = acc[mf][nf][half * 2] + b0;
                    float v1 = acc[mf][nf][half * 2 + 1] + b1;
                    if (EPI == 2) {
                        float ig = sigmoid_f(v0), rg = sigmoid_f(v1);
                        float a = expf(-8.0f * sp * rg);
                        float gx = sqrtf(fmaxf(1.0f - a * a, 0.f)) * ig * aux[(size_t)row * DR + c];
                        C[(size_t)row * DR + c] = a;
                        C2[(size_t)row * DR + c] = gx;
                    } else if (EPI == 4) {
                        Cb2[(size_t)row * DR + c] = __float2half(gelu_f(v0));
                        Cb[(size_t)row * DR + c] = __float2half(v1);
                    } else {  // EPI 5
                        Cb[(size_t)row * MI + c] = __float2half(gelu_f(v0) * v1);
                    }
                }
        }
    }
}

// ------------------- RMSNorm (fp16 output: feeds GEMMs) -------------------
__global__ __launch_bounds__(256) void rmsnorm_k(const float* __restrict__ x,
                                                 const float* __restrict__ w,
                                                 __half* __restrict__ o, int D) {
    int row = blockIdx.x;
    const float* xr = x + (size_t)row * D;
    float s = 0.f;
    for (int i = threadIdx.x; i < D; i += 256) { float v = xr[i]; s += v * v; }
    __shared__ float sm[8];
    __shared__ float s_inv;
    for (int off = 16; off; off >>= 1) s += __shfl_down_sync(0xffffffffu, s, off);
    if ((threadIdx.x & 31) == 0) sm[threadIdx.x >> 5] = s;
    __syncthreads();
    if (threadIdx.x == 0) {
        float t = 0.f;
#pragma unroll
        for (int i = 0; i < 8; i++) t += sm[i];
        s_inv = rsqrtf(t / (float)D + 1e-5f);
    }
    __syncthreads();
    float inv = s_inv;
    __half* orow = o + (size_t)row * D;
    for (int i = threadIdx.x; i < D; i += 256) orow[i] = __float2half(xr[i] * inv * w[i]);
}

// ------------------- weight conversion kernels -------------------
__global__ __launch_bounds__(256) void cvt_w_k(const float* __restrict__ src,
                                               __half* __restrict__ dst, int n) {
    int i = (blockIdx.x * 256 + threadIdx.x) * 4;
    if (i >= n) return;
    float4 v = *(const float4*)(src + i);
    __half2 h0; h0.x = __float2half(v.x); h0.y = __float2half(v.y);
    __half2 h1; h1.x = __float2half(v.z); h1.y = __float2half(v.w);
    *(__half2*)(dst + i) = h0;
    *(__half2*)(dst + i + 2) = h1;
}
// interleave rows: dst[2c+p][k] = src[p*Nh + c][k]
__global__ __launch_bounds__(256) void cvt_w_pair_k(const float* __restrict__ src,
                                                    __half* __restrict__ dst, int Nh, int K) {
    int i = blockIdx.x * 256 + threadIdx.x;
    if (i >= 2 * Nh * K) return;
    int n = i / K, k = i - n * K;
    int c = n >> 1, p = n & 1;
    dst[i] = __float2half(src[(size_t)(p * Nh + c) * K + k]);
}
__global__ __launch_bounds__(256) void repack_wconv_k(const float* __restrict__ w_conv) {
    int i = blockIdx.x * 256 + threadIdx.x;
    if (i >= DR * 4 * DR) return;
    int n = i >> 12;
    int rem = i & 4095;
    int t = rem >> 10;
    int kin = rem & 1023;
    g_wk[i] = __float2half(w_conv[((size_t)n << 12) + (kin << 2) + t]);
}

// ------------------- chunked linear-recurrence scan -------------------
__global__ __launch_bounds__(256) void scan_pass1_k() {
    int c = blockIdx.y * 256 + threadIdx.x;
    int j = blockIdx.x;
    size_t base = (size_t)j * SCHUNK * DR + c;
    float A = 1.f, B = 0.f;
#pragma unroll 4
    for (int t = 0; t < SCHUNK; t++) {
        float at = g_a[base + (size_t)t * DR];
        float gx = g_gx[base + (size_t)t * DR];
        B = fmaf(at, B, gx);
        A *= at;
    }
    g_Ag[j * DR + c] = A;
    g_Bg[j * DR + c] = B;
}
__global__ __launch_bounds__(256) void scan_pass2_k() {
    int c = blockIdx.x * 256 + threadIdx.x;
    float h = 0.f;
    for (int j = 0; j < NCHUNK; j++) {
        g_carry[j * DR + c] = h;
        h = fmaf(g_Ag[j * DR + c], h, g_Bg[j * DR + c]);
    }
}
// pass3 fused with ya = a_branch * y, fp16 store
__global__ __launch_bounds__(256) void scan_pass3_k() {
    int c = blockIdx.y * 256 + threadIdx.x;
    int j = blockIdx.x;
    size_t base = (size_t)j * SCHUNK * DR + c;
    float h = g_carry[j * DR + c];
#pragma unroll 4
    for (int t = 0; t < SCHUNK; t++) {
        float at = g_a[base + (size_t)t * DR];
        float gx = g_gx[base + (size_t)t * DR];
        h = fmaf(at, h, gx);
        g_ya[base + (size_t)t * DR] = __float2half(h * __half2float(g_abr[base + (size_t)t * DR]));
    }
}

// ------------------- launch -------------------
#define SMEM_BYTES (STAGES * ASTG * 2 * 2)

extern "C" void kernel_launch(void* const* d_in, const int* in_sizes, int n_in,
                              void* d_out, int out_size) {
    const float* x      = (const float*)d_in[0];
    const float* w_n1   = (const float*)d_in[1];
    const float* w_n2   = (const float*)d_in[2];
    const float* w_lin1 = (const float*)d_in[3];
    const float* b_lin1 = (const float*)d_in[4];
    const float* w_conv = (const float*)d_in[5];
    const float* w_rg   = (const float*)d_in[6];
    const float* b_rg   = (const float*)d_in[7];
    const float* Lambda = (const float*)d_in[8];
    const float* w_out  = (const float*)d_in[9];
    const float* b_out  = (const float*)d_in[10];
    const float* w_m1   = (const float*)d_in[11];
    const float* b_m1   = (const float*)d_in[12];
    const float* w_m2   = (const float*)d_in[13];
    const float* b_m2   = (const float*)d_in[14];
    float* out = (float*)d_out;

    __half *p_hh, *p_abr, *p_bb, *p_convh, *p_ya, *p_mi;
    __half *p_wlin1i, *p_wrgi, *p_wout, *p_wm1i, *p_wm2, *p_wk;
    float *p_conv, *p_a, *p_gx, *p_x2;
    cudaGetSymbolAddress((void**)&p_hh, g_hh);
    cudaGetSymbolAddress((void**)&p_abr, g_abr);
    cudaGetSymbolAddress((void**)&p_bb, g_bb);
    cudaGetSymbolAddress((void**)&p_conv, g_conv);
    cudaGetSymbolAddress((void**)&p_convh, g_convh);
    cudaGetSymbolAddress((void**)&p_a, g_a);
    cudaGetSymbolAddress((void**)&p_gx, g_gx);
    cudaGetSymbolAddress((void**)&p_ya, g_ya);
    cudaGetSymbolAddress((void**)&p_x2, g_x2);
    cudaGetSymbolAddress((void**)&p_mi, g_mi);
    cudaGetSymbolAddress((void**)&p_wlin1i, g_wlin1i);
    cudaGetSymbolAddress((void**)&p_wrgi, g_wrgi);
    cudaGetSymbolAddress((void**)&p_wout, g_wout);
    cudaGetSymbolAddress((void**)&p_wm1i, g_wm1i);
    cudaGetSymbolAddress((void**)&p_wm2, g_wm2);
    cudaGetSymbolAddress((void**)&p_wk, g_wk);

    cudaFuncSetAttribute(tc_gemm<0>, cudaFuncAttributeMaxDynamicSharedMemorySize, SMEM_BYTES);
    cudaFuncSetAttribute(tc_gemm<2>, cudaFuncAttributeMaxDynamicSharedMemorySize, SMEM_BYTES);
    cudaFuncSetAttribute(tc_gemm<3>, cudaFuncAttributeMaxDynamicSharedMemorySize, SMEM_BYTES);
    cudaFuncSetAttribute(tc_gemm<4>, cudaFuncAttributeMaxDynamicSharedMemorySize, SMEM_BYTES);
    cudaFuncSetAttribute(tc_gemm<5>, cudaFuncAttributeMaxDynamicSharedMemorySize, SMEM_BYTES);

    // Launch order arranged so ncu's capture window (-s 5 -c 1, launch index 5)
    // lands on the conv GEMM (largest mainloop, K=4096).
    // [0] lin1 weight interleave
    cvt_w_pair_k<<<(2 * DR * DM + 255) / 256, 256>>>(w_lin1, p_wlin1i, DR, DM);
    // [1] conv weight repack
    repack_wconv_k<<<(DR * 4 * DR + 255) / 256, 256>>>(w_conv);
    // [2] h = rmsnorm(x, w_n1) -> fp16
    rmsnorm_k<<<S, 256>>>(x, w_n1, p_hh, DM);
    // [3] lin1 (interleaved): abr = gelu(a+b), bb = b_branch, both fp16
    tc_gemm<4><<<dim3(2 * DR / 128, S / 128), 256, SMEM_BYTES>>>(
        p_hh, DM, p_wlin1i, b_lin1, nullptr, nullptr, DR, nullptr, p_bb, p_abr,
        nullptr, nullptr, DM, 0);
    // [4] rg weight interleave
    cvt_w_pair_k<<<(2 * DR * DR + 255) / 256, 256>>>(w_rg, p_wrgi, DR, DR);
    // [5] conv = causal conv as K=4096 GEMM (shifted A rows, zfill t<0)  <-- ncu window
    tc_gemm<0><<<dim3(DR / 128, S / 128), 256, SMEM_BYTES>>>(
        p_bb, DR, p_wk, nullptr, nullptr, p_conv, DR, nullptr, p_convh, nullptr,
        nullptr, nullptr, 4 * DR, 1);
    // [6] gates GEMM (interleaved) with fused a/gated_x epilogue
    tc_gemm<2><<<dim3(2 * DR / 128, S / 128), 256, SMEM_BYTES>>>(
        p_convh, DR, p_wrgi, b_rg, nullptr, p_a, DR, p_gx, nullptr, nullptr,
        p_conv, Lambda, DR, 0);
    // [7..9] linear recurrence scan (pass3 fused with ya = abr*y -> fp16)
    scan_pass1_k<<<dim3(NCHUNK, DR / 256), 256>>>();
    scan_pass2_k<<<DR / 256, 256>>>();
    scan_pass3_k<<<dim3(NCHUNK, DR / 256), 256>>>();
    // [10] out weight cvt
    cvt_w_k<<<(DM * DR / 4 + 255) / 256, 256>>>(w_out, p_wout, DM * DR);
    // [11] x2 = x + ya @ w_out^T + b_out   (fp32 residual path)
    tc_gemm<3><<<dim3(DM / 128, S / 128), 256, SMEM_BYTES>>>(
        p_ya, DR, p_wout, b_out, x, p_x2, DM, nullptr, nullptr, nullptr,
        nullptr, nullptr, DR, 0);
    // [12] h2 = rmsnorm(x2, w_n2) -> fp16
    rmsnorm_k<<<S, 256>>>(p_x2, w_n2, p_hh, DM);
    // [13] m1 weight interleave
    cvt_w_pair_k<<<(2 * MI * DM + 255) / 256, 256>>>(w_m1, p_wm1i, MI, DM);
    // [14] m1 (interleaved) with fused GLU: mi = gelu(u)*v -> fp16
    tc_gemm<5><<<dim3(2 * MI / 128, S / 128), 256, SMEM_BYTES>>>(
        p_hh, DM, p_wm1i, b_m1, nullptr, nullptr, MI, nullptr, p_mi, nullptr,
        nullptr, nullptr, DM, 0);
    // [15] m2 weight cvt
    cvt_w_k<<<(DM * MI / 4 + 255) / 256, 256>>>(w_m2, p_wm2, DM * MI);
    // [16] out = x2 + mi @ w_m2^T + b_m2   (fp32 residual path)
    tc_gemm<3><<<dim3(DM / 128, S / 128), 256, SMEM_BYTES>>>(
        p_mi, MI, p_wm2, b_m2, p_x2, out, DM, nullptr, nullptr, nullptr,
        nullptr, nullptr, MI, 0);
}